// round 8
// baseline (speedup 1.0000x reference)
#include <cuda_runtime.h>
#include <math.h>

// Problem constants
#define BN 4
#define KN 16
#define HW (512*512)
#define HW4 (HW/4)
#define LOG_2PI 1.8378770664093453f
#define LOG2E 1.4426950408889634f

// Reduction config
#define KG 8            // k-groups
#define KPT 2           // k per thread (KG*KPT == KN)
#define CHUNKS 32       // pixel chunks per (b, kgroup)
#define RTHREADS 256
#define RITERS (HW4 / (CHUNKS * RTHREADS))   // = 8, exact
#define NSTAT 10

#define CTHREADS 128    // pass C block: 4 warps
#define QPB 32          // pixel-quads per block (one per lane)

// Deterministic scratch (no allocations allowed).
// Layout: g_part[bkg][j*NSTAT+s][chunk]  (chunk contiguous -> float4 reads)
__device__ float g_part[BN * KG * KPT * NSTAT * CHUNKS];

typedef unsigned long long u64;

__device__ __forceinline__ u64 pack2(float lo, float hi) {
    u64 r; asm("mov.b64 %0,{%1,%2};" : "=l"(r) : "f"(lo), "f"(hi)); return r;
}
__device__ __forceinline__ void unpack2(u64 v, float& lo, float& hi) {
    asm("mov.b64 {%0,%1},%2;" : "=f"(lo), "=f"(hi) : "l"(v));
}
__device__ __forceinline__ u64 fma2(u64 a, u64 b, u64 c) {
    u64 d; asm("fma.rn.f32x2 %0,%1,%2,%3;" : "=l"(d) : "l"(a), "l"(b), "l"(c)); return d;
}
__device__ __forceinline__ u64 mul2(u64 a, u64 b) {
    u64 d; asm("mul.rn.f32x2 %0,%1,%2;" : "=l"(d) : "l"(a), "l"(b)); return d;
}
__device__ __forceinline__ u64 add2(u64 a, u64 b) {
    u64 d; asm("add.rn.f32x2 %0,%1,%2;" : "=l"(d) : "l"(a), "l"(b)); return d;
}
__device__ __forceinline__ float ex2(float x) {
    float y; asm("ex2.approx.f32 %0,%1;" : "=f"(y) : "f"(x)); return y;
}
__device__ __forceinline__ u64 exp2_2(u64 t) {
    float lo, hi; unpack2(t, lo, hi);
    return pack2(ex2(lo), ex2(hi));
}
__device__ __forceinline__ float rcp(float x) {
    float y; asm("rcp.approx.f32 %0,%1;" : "=f"(y) : "f"(x)); return y;
}

// ---------------------------------------------------------------------------
// Pass A: per-(b,k) partial sufficient statistics, float4 loads, scalar FMA.
// grid = (CHUNKS, KG, BN), block = RTHREADS. No atomics -> deterministic.
// (Unchanged from best measured config: 21.8us.)
// ---------------------------------------------------------------------------
__global__ __launch_bounds__(RTHREADS)
void gmm_reduce_kernel(const float* __restrict__ P, const float* __restrict__ I) {
    const int b = blockIdx.z, kg = blockIdx.y, chunk = blockIdx.x;
    const int tid = threadIdx.x;

    const float4* __restrict__ I0 = (const float4*)(I + (size_t)(b * 3 + 0) * HW);
    const float4* __restrict__ I1 = (const float4*)(I + (size_t)(b * 3 + 1) * HW);
    const float4* __restrict__ I2 = (const float4*)(I + (size_t)(b * 3 + 2) * HW);
    const float4* __restrict__ Pb = (const float4*)(P + ((size_t)b * KN + (size_t)kg * KPT) * HW);

    float acc[KPT][NSTAT];
#pragma unroll
    for (int j = 0; j < KPT; j++)
#pragma unroll
        for (int s = 0; s < NSTAT; s++) acc[j][s] = 0.0f;

    const int stride = CHUNKS * RTHREADS;
    int p = chunk * RTHREADS + tid;
#pragma unroll 2
    for (int it = 0; it < RITERS; it++, p += stride) {
        const float4 a0 = I0[p];
        const float4 a1 = I1[p];
        const float4 a2 = I2[p];
        float4 w[KPT];
#pragma unroll
        for (int j = 0; j < KPT; j++)
            w[j] = __ldcs(&Pb[(size_t)j * HW4 + p]);

        const float x0[4] = {a0.x, a0.y, a0.z, a0.w};
        const float x1[4] = {a1.x, a1.y, a1.z, a1.w};
        const float x2[4] = {a2.x, a2.y, a2.z, a2.w};
#pragma unroll
        for (int l = 0; l < 4; l++) {
            const float v0 = x0[l], v1 = x1[l], v2 = x2[l];
            const float p00 = v0 * v0, p01 = v0 * v1, p02 = v0 * v2;
            const float p11 = v1 * v1, p12 = v1 * v2, p22 = v2 * v2;
#pragma unroll
            for (int j = 0; j < KPT; j++) {
                const float wl = (l == 0) ? w[j].x : (l == 1) ? w[j].y : (l == 2) ? w[j].z : w[j].w;
                acc[j][0] += wl;
                acc[j][1] = fmaf(wl, v0, acc[j][1]);
                acc[j][2] = fmaf(wl, v1, acc[j][2]);
                acc[j][3] = fmaf(wl, v2, acc[j][3]);
                acc[j][4] = fmaf(wl, p00, acc[j][4]);
                acc[j][5] = fmaf(wl, p01, acc[j][5]);
                acc[j][6] = fmaf(wl, p02, acc[j][6]);
                acc[j][7] = fmaf(wl, p11, acc[j][7]);
                acc[j][8] = fmaf(wl, p12, acc[j][8]);
                acc[j][9] = fmaf(wl, p22, acc[j][9]);
            }
        }
    }

#pragma unroll
    for (int j = 0; j < KPT; j++)
#pragma unroll
        for (int s = 0; s < NSTAT; s++)
#pragma unroll
            for (int off = 16; off > 0; off >>= 1)
                acc[j][s] += __shfl_down_sync(0xffffffffu, acc[j][s], off);

    __shared__ float sh[RTHREADS / 32][KPT * NSTAT];
    const int warp = tid >> 5, lane = tid & 31;
    if (lane == 0) {
#pragma unroll
        for (int j = 0; j < KPT; j++)
#pragma unroll
            for (int s = 0; s < NSTAT; s++)
                sh[warp][j * NSTAT + s] = acc[j][s];
    }
    __syncthreads();

    if (tid < KPT * NSTAT) {
        float v = 0.0f;
#pragma unroll
        for (int w = 0; w < RTHREADS / 32; w++) v += sh[w][tid];
        g_part[(((size_t)(b * KG + kg) * (KPT * NSTAT)) + tid) * CHUNKS + chunk] = v;
    }
}

// ---------------------------------------------------------------------------
// Pass C: fused params-finalize + E-step, classes split across warps.
// Block = 4 warps; warp w owns classes [4w, 4w+4); lane owns one pixel-quad.
// Denominator exchanged across warps via one smem round-trip.
// grid = (HW4/QPB, BN), block = CTHREADS
// ---------------------------------------------------------------------------
__global__ __launch_bounds__(CTHREADS)
void gmm_estep_kernel(const float* __restrict__ I, float* __restrict__ out) {
    const int b = blockIdx.y;
    const int tid = threadIdx.x;
    const int lane = tid & 31;
    const int w = tid >> 5;

    __shared__ float raws[KN][NSTAT];
    __shared__ __align__(16) u64 spd[KN][NSTAT];     // 80B rows, 16B-aligned
    __shared__ __align__(16) ulonglong2 exch[4][QPB];

    // ---- fused pass B, stage 1: reduce partial stats (160 items) ----
    for (int t = tid; t < KN * NSTAT; t += CTHREADS) {
        const int k = t / NSTAT, s = t % NSTAT;
        const int kg = k / KPT, j = k % KPT;
        const float4* gp = (const float4*)&g_part[
            (((size_t)(b * KG + kg) * (KPT * NSTAT)) + j * NSTAT + s) * CHUNKS];
        float4 a = make_float4(0.f, 0.f, 0.f, 0.f);
#pragma unroll
        for (int c = 0; c < CHUNKS / 4; c++) {
            const float4 v = gp[c];
            a.x += v.x; a.y += v.y; a.z += v.z; a.w += v.w;
        }
        raws[k][s] = (a.x + a.y) + (a.z + a.w);
    }
    __syncthreads();

    // ---- fused pass B, stage 2: 3x3 inverse + log2-domain affine params ----
    if (tid < KN) {
        const float* s = raws[tid];
        const float SP = s[0];
        const float rd = 1.0f / (1e-5f + SP);
        const float mu0 = s[1] * rd, mu1 = s[2] * rd, mu2 = s[3] * rd;

        const float c00 = (s[4] - 2.0f * mu0 * s[1] + SP * mu0 * mu0) * rd + 1e-3f;
        const float c01 = (s[5] - mu0 * s[2] - mu1 * s[1] + SP * mu0 * mu1) * rd;
        const float c02 = (s[6] - mu0 * s[3] - mu2 * s[1] + SP * mu0 * mu2) * rd;
        const float c11 = (s[7] - 2.0f * mu1 * s[2] + SP * mu1 * mu1) * rd + 1e-3f;
        const float c12 = (s[8] - mu1 * s[3] - mu2 * s[2] + SP * mu1 * mu2) * rd;
        const float c22 = (s[9] - 2.0f * mu2 * s[3] + SP * mu2 * mu2) * rd + 1e-3f;

        const float m00 = c11 * c22 - c12 * c12;
        const float m01 = c02 * c12 - c01 * c22;
        const float m02 = c01 * c12 - c02 * c11;
        const float det = c00 * m00 + c01 * m01 + c02 * m02;
        const float inv = 1.0f / det;

        const float i00 = m00 * inv;
        const float i01 = m01 * inv;
        const float i02 = m02 * inv;
        const float i11 = (c00 * c22 - c02 * c02) * inv;
        const float i12 = (c01 * c02 - c00 * c12) * inv;
        const float i22 = (c00 * c11 - c01 * c01) * inv;

        const float alpha = SP * (1.0f / (float)HW);
        const float logcoef = logf(alpha) - 0.5f * (3.0f * LOG_2PI + logf(det));

        const float g0 = i00 * mu0 + i01 * mu1 + i02 * mu2;
        const float g1 = i01 * mu0 + i11 * mu1 + i12 * mu2;
        const float g2 = i02 * mu0 + i12 * mu1 + i22 * mu2;
        const float Pmu = 0.5f * (i00 * mu0 * mu0 + i11 * mu1 * mu1 + i22 * mu2 * mu2)
                        + i01 * mu0 * mu1 + i02 * mu0 * mu2 + i12 * mu1 * mu2;

        u64* o = spd[tid];
        const float pc0 = (logcoef - Pmu) * LOG2E;
        const float pg0 = g0 * LOG2E, pg1 = g1 * LOG2E, pg2 = g2 * LOG2E;
        const float h00 = -0.5f * i00 * LOG2E, h11 = -0.5f * i11 * LOG2E, h22 = -0.5f * i22 * LOG2E;
        const float h01 = -i01 * LOG2E, h02 = -i02 * LOG2E, h12 = -i12 * LOG2E;
        o[0] = pack2(pc0, pc0);
        o[1] = pack2(pg0, pg0);
        o[2] = pack2(pg1, pg1);
        o[3] = pack2(pg2, pg2);
        o[4] = pack2(h00, h00);
        o[5] = pack2(h11, h11);
        o[6] = pack2(h22, h22);
        o[7] = pack2(h01, h01);
        o[8] = pack2(h02, h02);
        o[9] = pack2(h12, h12);
    }
    __syncthreads();

    // ---- E-step main: lane -> pixel-quad, warp -> 4 classes ----
    const int p = blockIdx.x * QPB + lane;

    const float4 a0 = ((const float4*)(I + (size_t)(b * 3 + 0) * HW))[p];
    const float4 a1 = ((const float4*)(I + (size_t)(b * 3 + 1) * HW))[p];
    const float4 a2 = ((const float4*)(I + (size_t)(b * 3 + 2) * HW))[p];

    u64 X0[2], X1[2], X2[2], XX00[2], XX01[2], XX02[2], XX11[2], XX12[2], XX22[2];
#pragma unroll
    for (int pi = 0; pi < 2; pi++) {
        X0[pi] = pi ? pack2(a0.z, a0.w) : pack2(a0.x, a0.y);
        X1[pi] = pi ? pack2(a1.z, a1.w) : pack2(a1.x, a1.y);
        X2[pi] = pi ? pack2(a2.z, a2.w) : pack2(a2.x, a2.y);
        XX00[pi] = mul2(X0[pi], X0[pi]);
        XX01[pi] = mul2(X0[pi], X1[pi]);
        XX02[pi] = mul2(X0[pi], X2[pi]);
        XX11[pi] = mul2(X1[pi], X1[pi]);
        XX12[pi] = mul2(X1[pi], X2[pi]);
        XX22[pi] = mul2(X2[pi], X2[pi]);
    }

    u64 q0[4], q1[4];
    u64 psum0 = 0ull, psum1 = 0ull;
#pragma unroll
    for (int kc = 0; kc < 4; kc++) {
        const int k = w * 4 + kc;
        const ulonglong2* pr = (const ulonglong2*)spd[k];
        const ulonglong2 pA = pr[0];  // C0,  G0
        const ulonglong2 pB = pr[1];  // G1,  G2
        const ulonglong2 pC = pr[2];  // H00, H11
        const ulonglong2 pD = pr[3];  // H22, H01
        const ulonglong2 pE = pr[4];  // H02, H12

        {
            u64 ta = fma2(pA.y, X0[0], pA.x);
            ta = fma2(pB.x, X1[0], ta);
            ta = fma2(pB.y, X2[0], ta);
            ta = fma2(pC.x, XX00[0], ta);
            u64 tb = mul2(pC.y, XX11[0]);
            tb = fma2(pD.x, XX22[0], tb);
            tb = fma2(pD.y, XX01[0], tb);
            tb = fma2(pE.x, XX02[0], tb);
            tb = fma2(pE.y, XX12[0], tb);
            const u64 e = exp2_2(add2(ta, tb));
            q0[kc] = e;
            psum0 = add2(psum0, e);
        }
        {
            u64 ta = fma2(pA.y, X0[1], pA.x);
            ta = fma2(pB.x, X1[1], ta);
            ta = fma2(pB.y, X2[1], ta);
            ta = fma2(pC.x, XX00[1], ta);
            u64 tb = mul2(pC.y, XX11[1]);
            tb = fma2(pD.x, XX22[1], tb);
            tb = fma2(pD.y, XX01[1], tb);
            tb = fma2(pE.x, XX02[1], tb);
            tb = fma2(pE.y, XX12[1], tb);
            const u64 e = exp2_2(add2(ta, tb));
            q1[kc] = e;
            psum1 = add2(psum1, e);
        }
    }

    // ---- cross-warp denominator exchange (deterministic fixed-order sum) ----
    exch[w][lane] = make_ulonglong2(psum0, psum1);
    __syncthreads();
    const ulonglong2 e0 = exch[0][lane];
    const ulonglong2 e1 = exch[1][lane];
    const ulonglong2 e2 = exch[2][lane];
    const ulonglong2 e3 = exch[3][lane];
    const u64 sum0 = add2(add2(e0.x, e1.x), add2(e2.x, e3.x));
    const u64 sum1 = add2(add2(e0.y, e1.y), add2(e2.y, e3.y));

    float s0, s1, s2, s3;
    unpack2(sum0, s0, s1);
    unpack2(sum1, s2, s3);
    const u64 R0 = pack2(rcp(1e-5f + s0), rcp(1e-5f + s1));
    const u64 R1 = pack2(rcp(1e-5f + s2), rcp(1e-5f + s3));

    float4* __restrict__ o4 = (float4*)(out + (size_t)b * KN * HW);
#pragma unroll
    for (int kc = 0; kc < 4; kc++) {
        const u64 v01 = mul2(q0[kc], R0);
        const u64 v23 = mul2(q1[kc], R1);
        float4 v;
        unpack2(v01, v.x, v.y);
        unpack2(v23, v.z, v.w);
        __stcs(&o4[(size_t)(w * 4 + kc) * HW4 + p], v);
    }
}

extern "C" void kernel_launch(void* const* d_in, const int* in_sizes, int n_in,
                              void* d_out, int out_size) {
    const float* Pij = (const float*)d_in[0];
    const float* I   = (const float*)d_in[1];
    float* out = (float*)d_out;

    dim3 gA(CHUNKS, KG, BN);
    gmm_reduce_kernel<<<gA, RTHREADS>>>(Pij, I);
    dim3 gC(HW4 / QPB, BN);
    gmm_estep_kernel<<<gC, CTHREADS>>>(I, out);
}

// round 9
// speedup vs baseline: 1.4406x; 1.4406x over previous
#include <cuda_runtime.h>
#include <math.h>

// Problem constants
#define BN 4
#define KN 16
#define HW (512*512)
#define HW4 (HW/4)
#define LOG_2PI 1.8378770664093453f
#define LOG2E 1.4426950408889634f

// Reduction config
#define KG 8            // k-groups
#define KPT 2           // k per thread (KG*KPT == KN)
#define CHUNKS 64       // pixel chunks per (b, kgroup)
#define RTHREADS 256
#define RITERS (HW4 / (CHUNKS * RTHREADS))   // = 4, exact
#define NSTAT 10

#define CTHREADS 128    // pass C block: 4 warps
#define QPB 32          // pixel-quads per block (one per lane)

// Deterministic scratch (no allocations allowed).
// g_part[bkg][j*NSTAT+s][chunk]  (chunk contiguous)
__device__ float g_part[BN * KG * KPT * NSTAT * CHUNKS];

typedef unsigned long long u64;
// packed (lane-duplicated) log2-domain affine params: [b][k][10]
__device__ u64 g_params[BN * KN * NSTAT];

__device__ __forceinline__ u64 pack2(float lo, float hi) {
    u64 r; asm("mov.b64 %0,{%1,%2};" : "=l"(r) : "f"(lo), "f"(hi)); return r;
}
__device__ __forceinline__ void unpack2(u64 v, float& lo, float& hi) {
    asm("mov.b64 {%0,%1},%2;" : "=f"(lo), "=f"(hi) : "l"(v));
}
__device__ __forceinline__ u64 fma2(u64 a, u64 b, u64 c) {
    u64 d; asm("fma.rn.f32x2 %0,%1,%2,%3;" : "=l"(d) : "l"(a), "l"(b), "l"(c)); return d;
}
__device__ __forceinline__ u64 mul2(u64 a, u64 b) {
    u64 d; asm("mul.rn.f32x2 %0,%1,%2;" : "=l"(d) : "l"(a), "l"(b)); return d;
}
__device__ __forceinline__ u64 add2(u64 a, u64 b) {
    u64 d; asm("add.rn.f32x2 %0,%1,%2;" : "=l"(d) : "l"(a), "l"(b)); return d;
}
__device__ __forceinline__ float ex2(float x) {
    float y; asm("ex2.approx.f32 %0,%1;" : "=f"(y) : "f"(x)); return y;
}
__device__ __forceinline__ u64 exp2_2(u64 t) {
    float lo, hi; unpack2(t, lo, hi);
    return pack2(ex2(lo), ex2(hi));
}
__device__ __forceinline__ float rcp(float x) {
    float y; asm("rcp.approx.f32 %0,%1;" : "=f"(y) : "f"(x)); return y;
}

// ---------------------------------------------------------------------------
// Pass A: per-(b,k) partial sufficient statistics, float4 loads, scalar FMA.
// grid = (CHUNKS, KG, BN), block = RTHREADS. No atomics -> deterministic.
// ---------------------------------------------------------------------------
__global__ __launch_bounds__(RTHREADS)
void gmm_reduce_kernel(const float* __restrict__ P, const float* __restrict__ I) {
    const int b = blockIdx.z, kg = blockIdx.y, chunk = blockIdx.x;
    const int tid = threadIdx.x;

    const float4* __restrict__ I0 = (const float4*)(I + (size_t)(b * 3 + 0) * HW);
    const float4* __restrict__ I1 = (const float4*)(I + (size_t)(b * 3 + 1) * HW);
    const float4* __restrict__ I2 = (const float4*)(I + (size_t)(b * 3 + 2) * HW);
    const float4* __restrict__ Pb = (const float4*)(P + ((size_t)b * KN + (size_t)kg * KPT) * HW);

    float acc[KPT][NSTAT];
#pragma unroll
    for (int j = 0; j < KPT; j++)
#pragma unroll
        for (int s = 0; s < NSTAT; s++) acc[j][s] = 0.0f;

    const int stride = CHUNKS * RTHREADS;
    int p = chunk * RTHREADS + tid;
#pragma unroll 2
    for (int it = 0; it < RITERS; it++, p += stride) {
        const float4 a0 = I0[p];
        const float4 a1 = I1[p];
        const float4 a2 = I2[p];
        float4 w[KPT];
#pragma unroll
        for (int j = 0; j < KPT; j++)
            w[j] = __ldcs(&Pb[(size_t)j * HW4 + p]);

        const float x0[4] = {a0.x, a0.y, a0.z, a0.w};
        const float x1[4] = {a1.x, a1.y, a1.z, a1.w};
        const float x2[4] = {a2.x, a2.y, a2.z, a2.w};
#pragma unroll
        for (int l = 0; l < 4; l++) {
            const float v0 = x0[l], v1 = x1[l], v2 = x2[l];
            const float p00 = v0 * v0, p01 = v0 * v1, p02 = v0 * v2;
            const float p11 = v1 * v1, p12 = v1 * v2, p22 = v2 * v2;
#pragma unroll
            for (int j = 0; j < KPT; j++) {
                const float wl = (l == 0) ? w[j].x : (l == 1) ? w[j].y : (l == 2) ? w[j].z : w[j].w;
                acc[j][0] += wl;
                acc[j][1] = fmaf(wl, v0, acc[j][1]);
                acc[j][2] = fmaf(wl, v1, acc[j][2]);
                acc[j][3] = fmaf(wl, v2, acc[j][3]);
                acc[j][4] = fmaf(wl, p00, acc[j][4]);
                acc[j][5] = fmaf(wl, p01, acc[j][5]);
                acc[j][6] = fmaf(wl, p02, acc[j][6]);
                acc[j][7] = fmaf(wl, p11, acc[j][7]);
                acc[j][8] = fmaf(wl, p12, acc[j][8]);
                acc[j][9] = fmaf(wl, p22, acc[j][9]);
            }
        }
    }

#pragma unroll
    for (int j = 0; j < KPT; j++)
#pragma unroll
        for (int s = 0; s < NSTAT; s++)
#pragma unroll
            for (int off = 16; off > 0; off >>= 1)
                acc[j][s] += __shfl_down_sync(0xffffffffu, acc[j][s], off);

    __shared__ float sh[RTHREADS / 32][KPT * NSTAT];
    const int warp = tid >> 5, lane = tid & 31;
    if (lane == 0) {
#pragma unroll
        for (int j = 0; j < KPT; j++)
#pragma unroll
            for (int s = 0; s < NSTAT; s++)
                sh[warp][j * NSTAT + s] = acc[j][s];
    }
    __syncthreads();

    if (tid < KPT * NSTAT) {
        float v = 0.0f;
#pragma unroll
        for (int w = 0; w < RTHREADS / 32; w++) v += sh[w][tid];
        g_part[(((size_t)(b * KG + kg) * (KPT * NSTAT)) + tid) * CHUNKS + chunk] = v;
    }
}

// ---------------------------------------------------------------------------
// Pass B: finalize per-(b,k) params ONCE; write packed u64 affine params.
// 1 block, 64 threads (t = b*KN + k), deterministic order.
// ---------------------------------------------------------------------------
__global__ void gmm_params_kernel() {
    const int t = threadIdx.x;
    if (t >= BN * KN) return;
    const int b = t / KN, k = t % KN;
    const int kg = k / KPT, j = k % KPT;

    float s[NSTAT];
#pragma unroll
    for (int i = 0; i < NSTAT; i++) {
        const float4* gp = (const float4*)&g_part[
            (((size_t)(b * KG + kg) * (KPT * NSTAT)) + j * NSTAT + i) * CHUNKS];
        float4 a = make_float4(0.f, 0.f, 0.f, 0.f);
#pragma unroll
        for (int c = 0; c < CHUNKS / 4; c++) {
            const float4 v = gp[c];
            a.x += v.x; a.y += v.y; a.z += v.z; a.w += v.w;
        }
        s[i] = (a.x + a.y) + (a.z + a.w);
    }

    const float SP = s[0];
    const float rd = 1.0f / (1e-5f + SP);
    const float mu0 = s[1] * rd, mu1 = s[2] * rd, mu2 = s[3] * rd;

    const float c00 = (s[4] - 2.0f * mu0 * s[1] + SP * mu0 * mu0) * rd + 1e-3f;
    const float c01 = (s[5] - mu0 * s[2] - mu1 * s[1] + SP * mu0 * mu1) * rd;
    const float c02 = (s[6] - mu0 * s[3] - mu2 * s[1] + SP * mu0 * mu2) * rd;
    const float c11 = (s[7] - 2.0f * mu1 * s[2] + SP * mu1 * mu1) * rd + 1e-3f;
    const float c12 = (s[8] - mu1 * s[3] - mu2 * s[2] + SP * mu1 * mu2) * rd;
    const float c22 = (s[9] - 2.0f * mu2 * s[3] + SP * mu2 * mu2) * rd + 1e-3f;

    const float m00 = c11 * c22 - c12 * c12;
    const float m01 = c02 * c12 - c01 * c22;
    const float m02 = c01 * c12 - c02 * c11;
    const float det = c00 * m00 + c01 * m01 + c02 * m02;
    const float inv = 1.0f / det;

    const float i00 = m00 * inv;
    const float i01 = m01 * inv;
    const float i02 = m02 * inv;
    const float i11 = (c00 * c22 - c02 * c02) * inv;
    const float i12 = (c01 * c02 - c00 * c12) * inv;
    const float i22 = (c00 * c11 - c01 * c01) * inv;

    const float alpha = SP * (1.0f / (float)HW);
    const float logcoef = logf(alpha) - 0.5f * (3.0f * LOG_2PI + logf(det));

    const float g0 = i00 * mu0 + i01 * mu1 + i02 * mu2;
    const float g1 = i01 * mu0 + i11 * mu1 + i12 * mu2;
    const float g2 = i02 * mu0 + i12 * mu1 + i22 * mu2;
    const float Pmu = 0.5f * (i00 * mu0 * mu0 + i11 * mu1 * mu1 + i22 * mu2 * mu2)
                    + i01 * mu0 * mu1 + i02 * mu0 * mu2 + i12 * mu1 * mu2;

    u64* o = &g_params[(size_t)t * NSTAT];
    const float pc0 = (logcoef - Pmu) * LOG2E;
    const float pg0 = g0 * LOG2E, pg1 = g1 * LOG2E, pg2 = g2 * LOG2E;
    const float h00 = -0.5f * i00 * LOG2E, h11 = -0.5f * i11 * LOG2E, h22 = -0.5f * i22 * LOG2E;
    const float h01 = -i01 * LOG2E, h02 = -i02 * LOG2E, h12 = -i12 * LOG2E;
    o[0] = pack2(pc0, pc0);
    o[1] = pack2(pg0, pg0);
    o[2] = pack2(pg1, pg1);
    o[3] = pack2(pg2, pg2);
    o[4] = pack2(h00, h00);
    o[5] = pack2(h11, h11);
    o[6] = pack2(h22, h22);
    o[7] = pack2(h01, h01);
    o[8] = pack2(h02, h02);
    o[9] = pack2(h12, h12);
}

// ---------------------------------------------------------------------------
// Pass C: E-step, classes split across warps.
// Block = 4 warps; warp w owns classes [4w, 4w+4); lane owns one pixel-quad.
// Params loaded coalesced into smem once per block (no redundant finalize).
// grid = (HW4/QPB, BN), block = CTHREADS
// ---------------------------------------------------------------------------
__global__ __launch_bounds__(CTHREADS)
void gmm_estep_kernel(const float* __restrict__ I, float* __restrict__ out) {
    const int b = blockIdx.y;
    const int tid = threadIdx.x;
    const int lane = tid & 31;
    const int w = tid >> 5;

    __shared__ __align__(16) u64 spd[KN * NSTAT];
    __shared__ __align__(16) ulonglong2 exch[4][QPB];

    // coalesced param load: 160 u64
#pragma unroll
    for (int t = tid; t < KN * NSTAT; t += CTHREADS)
        spd[t] = g_params[(size_t)b * KN * NSTAT + t];
    __syncthreads();

    const int p = blockIdx.x * QPB + lane;

    const float4 a0 = ((const float4*)(I + (size_t)(b * 3 + 0) * HW))[p];
    const float4 a1 = ((const float4*)(I + (size_t)(b * 3 + 1) * HW))[p];
    const float4 a2 = ((const float4*)(I + (size_t)(b * 3 + 2) * HW))[p];

    u64 X0[2], X1[2], X2[2], XX00[2], XX01[2], XX02[2], XX11[2], XX12[2], XX22[2];
#pragma unroll
    for (int pi = 0; pi < 2; pi++) {
        X0[pi] = pi ? pack2(a0.z, a0.w) : pack2(a0.x, a0.y);
        X1[pi] = pi ? pack2(a1.z, a1.w) : pack2(a1.x, a1.y);
        X2[pi] = pi ? pack2(a2.z, a2.w) : pack2(a2.x, a2.y);
        XX00[pi] = mul2(X0[pi], X0[pi]);
        XX01[pi] = mul2(X0[pi], X1[pi]);
        XX02[pi] = mul2(X0[pi], X2[pi]);
        XX11[pi] = mul2(X1[pi], X1[pi]);
        XX12[pi] = mul2(X1[pi], X2[pi]);
        XX22[pi] = mul2(X2[pi], X2[pi]);
    }

    u64 q0[4], q1[4];
    u64 psum0 = 0ull, psum1 = 0ull;
#pragma unroll
    for (int kc = 0; kc < 4; kc++) {
        const int k = w * 4 + kc;
        const ulonglong2* pr = (const ulonglong2*)&spd[k * NSTAT];
        const ulonglong2 pA = pr[0];  // C0,  G0
        const ulonglong2 pB = pr[1];  // G1,  G2
        const ulonglong2 pC = pr[2];  // H00, H11
        const ulonglong2 pD = pr[3];  // H22, H01
        const ulonglong2 pE = pr[4];  // H02, H12

        {
            u64 ta = fma2(pA.y, X0[0], pA.x);
            ta = fma2(pB.x, X1[0], ta);
            ta = fma2(pB.y, X2[0], ta);
            ta = fma2(pC.x, XX00[0], ta);
            u64 tb = mul2(pC.y, XX11[0]);
            tb = fma2(pD.x, XX22[0], tb);
            tb = fma2(pD.y, XX01[0], tb);
            tb = fma2(pE.x, XX02[0], tb);
            tb = fma2(pE.y, XX12[0], tb);
            const u64 e = exp2_2(add2(ta, tb));
            q0[kc] = e;
            psum0 = add2(psum0, e);
        }
        {
            u64 ta = fma2(pA.y, X0[1], pA.x);
            ta = fma2(pB.x, X1[1], ta);
            ta = fma2(pB.y, X2[1], ta);
            ta = fma2(pC.x, XX00[1], ta);
            u64 tb = mul2(pC.y, XX11[1]);
            tb = fma2(pD.x, XX22[1], tb);
            tb = fma2(pD.y, XX01[1], tb);
            tb = fma2(pE.x, XX02[1], tb);
            tb = fma2(pE.y, XX12[1], tb);
            const u64 e = exp2_2(add2(ta, tb));
            q1[kc] = e;
            psum1 = add2(psum1, e);
        }
    }

    // cross-warp denominator exchange (deterministic fixed-order sum)
    exch[w][lane] = make_ulonglong2(psum0, psum1);
    __syncthreads();
    const ulonglong2 e0 = exch[0][lane];
    const ulonglong2 e1 = exch[1][lane];
    const ulonglong2 e2 = exch[2][lane];
    const ulonglong2 e3 = exch[3][lane];
    const u64 sum0 = add2(add2(e0.x, e1.x), add2(e2.x, e3.x));
    const u64 sum1 = add2(add2(e0.y, e1.y), add2(e2.y, e3.y));

    float s0, s1, s2, s3;
    unpack2(sum0, s0, s1);
    unpack2(sum1, s2, s3);
    const u64 R0 = pack2(rcp(1e-5f + s0), rcp(1e-5f + s1));
    const u64 R1 = pack2(rcp(1e-5f + s2), rcp(1e-5f + s3));

    float4* __restrict__ o4 = (float4*)(out + (size_t)b * KN * HW);
#pragma unroll
    for (int kc = 0; kc < 4; kc++) {
        const u64 v01 = mul2(q0[kc], R0);
        const u64 v23 = mul2(q1[kc], R1);
        float4 v;
        unpack2(v01, v.x, v.y);
        unpack2(v23, v.z, v.w);
        __stcs(&o4[(size_t)(w * 4 + kc) * HW4 + p], v);
    }
}

extern "C" void kernel_launch(void* const* d_in, const int* in_sizes, int n_in,
                              void* d_out, int out_size) {
    const float* Pij = (const float*)d_in[0];
    const float* I   = (const float*)d_in[1];
    float* out = (float*)d_out;

    dim3 gA(CHUNKS, KG, BN);
    gmm_reduce_kernel<<<gA, RTHREADS>>>(Pij, I);
    gmm_params_kernel<<<1, 64>>>();
    dim3 gC(HW4 / QPB, BN);
    gmm_estep_kernel<<<gC, CTHREADS>>>(I, out);
}

// round 10
// speedup vs baseline: 1.7633x; 1.2240x over previous
#include <cuda_runtime.h>
#include <math.h>

// Problem constants
#define BN 4
#define KN 16
#define HW (512*512)
#define HW4 (HW/4)
#define LOG_2PI 1.8378770664093453f
#define LOG2E 1.4426950408889634f

// Reduction config
#define KG 8            // k-groups
#define KPT 2           // k per thread (KG*KPT == KN)
#define CHUNKS 32       // pixel chunks per (b, kgroup)
#define RTHREADS 256
#define RITERS (HW4 / (CHUNKS * RTHREADS))   // = 8, exact
#define NSTAT 10
#define ROWW (BN * KG * KPT * NSTAT)         // 640: g_part row width (chunk-major)

#define CTHREADS 256    // pass C block

// Deterministic scratch (no allocations allowed).
// Chunk-major: g_part[chunk][ (b*KG+kg)*KPT*NSTAT + j*NSTAT + s ]
__device__ float g_part[CHUNKS * ROWW];

typedef unsigned long long u64;

__device__ __forceinline__ u64 pack2(float lo, float hi) {
    u64 r; asm("mov.b64 %0,{%1,%2};" : "=l"(r) : "f"(lo), "f"(hi)); return r;
}
__device__ __forceinline__ void unpack2(u64 v, float& lo, float& hi) {
    asm("mov.b64 {%0,%1},%2;" : "=f"(lo), "=f"(hi) : "l"(v));
}
__device__ __forceinline__ u64 fma2(u64 a, u64 b, u64 c) {
    u64 d; asm("fma.rn.f32x2 %0,%1,%2,%3;" : "=l"(d) : "l"(a), "l"(b), "l"(c)); return d;
}
__device__ __forceinline__ u64 mul2(u64 a, u64 b) {
    u64 d; asm("mul.rn.f32x2 %0,%1,%2;" : "=l"(d) : "l"(a), "l"(b)); return d;
}
__device__ __forceinline__ u64 add2(u64 a, u64 b) {
    u64 d; asm("add.rn.f32x2 %0,%1,%2;" : "=l"(d) : "l"(a), "l"(b)); return d;
}
__device__ __forceinline__ float ex2(float x) {
    float y; asm("ex2.approx.f32 %0,%1;" : "=f"(y) : "f"(x)); return y;
}
__device__ __forceinline__ u64 exp2_2(u64 t) {
    float lo, hi; unpack2(t, lo, hi);
    return pack2(ex2(lo), ex2(hi));
}
__device__ __forceinline__ float rcp(float x) {
    float y; asm("rcp.approx.f32 %0,%1;" : "=f"(y) : "f"(x)); return y;
}

// ---------------------------------------------------------------------------
// Pass A: per-(b,k) partial sufficient statistics, float4 loads, scalar FMA.
// grid = (CHUNKS, KG, BN), block = RTHREADS. No atomics -> deterministic.
// (Measured-best config; only the g_part write index changed to chunk-major.)
// ---------------------------------------------------------------------------
__global__ __launch_bounds__(RTHREADS)
void gmm_reduce_kernel(const float* __restrict__ P, const float* __restrict__ I) {
    const int b = blockIdx.z, kg = blockIdx.y, chunk = blockIdx.x;
    const int tid = threadIdx.x;

    const float4* __restrict__ I0 = (const float4*)(I + (size_t)(b * 3 + 0) * HW);
    const float4* __restrict__ I1 = (const float4*)(I + (size_t)(b * 3 + 1) * HW);
    const float4* __restrict__ I2 = (const float4*)(I + (size_t)(b * 3 + 2) * HW);
    const float4* __restrict__ Pb = (const float4*)(P + ((size_t)b * KN + (size_t)kg * KPT) * HW);

    float acc[KPT][NSTAT];
#pragma unroll
    for (int j = 0; j < KPT; j++)
#pragma unroll
        for (int s = 0; s < NSTAT; s++) acc[j][s] = 0.0f;

    const int stride = CHUNKS * RTHREADS;
    int p = chunk * RTHREADS + tid;
#pragma unroll 2
    for (int it = 0; it < RITERS; it++, p += stride) {
        const float4 a0 = I0[p];
        const float4 a1 = I1[p];
        const float4 a2 = I2[p];
        float4 w[KPT];
#pragma unroll
        for (int j = 0; j < KPT; j++)
            w[j] = __ldcs(&Pb[(size_t)j * HW4 + p]);

        const float x0[4] = {a0.x, a0.y, a0.z, a0.w};
        const float x1[4] = {a1.x, a1.y, a1.z, a1.w};
        const float x2[4] = {a2.x, a2.y, a2.z, a2.w};
#pragma unroll
        for (int l = 0; l < 4; l++) {
            const float v0 = x0[l], v1 = x1[l], v2 = x2[l];
            const float p00 = v0 * v0, p01 = v0 * v1, p02 = v0 * v2;
            const float p11 = v1 * v1, p12 = v1 * v2, p22 = v2 * v2;
#pragma unroll
            for (int j = 0; j < KPT; j++) {
                const float wl = (l == 0) ? w[j].x : (l == 1) ? w[j].y : (l == 2) ? w[j].z : w[j].w;
                acc[j][0] += wl;
                acc[j][1] = fmaf(wl, v0, acc[j][1]);
                acc[j][2] = fmaf(wl, v1, acc[j][2]);
                acc[j][3] = fmaf(wl, v2, acc[j][3]);
                acc[j][4] = fmaf(wl, p00, acc[j][4]);
                acc[j][5] = fmaf(wl, p01, acc[j][5]);
                acc[j][6] = fmaf(wl, p02, acc[j][6]);
                acc[j][7] = fmaf(wl, p11, acc[j][7]);
                acc[j][8] = fmaf(wl, p12, acc[j][8]);
                acc[j][9] = fmaf(wl, p22, acc[j][9]);
            }
        }
    }

#pragma unroll
    for (int j = 0; j < KPT; j++)
#pragma unroll
        for (int s = 0; s < NSTAT; s++)
#pragma unroll
            for (int off = 16; off > 0; off >>= 1)
                acc[j][s] += __shfl_down_sync(0xffffffffu, acc[j][s], off);

    __shared__ float sh[RTHREADS / 32][KPT * NSTAT];
    const int warp = tid >> 5, lane = tid & 31;
    if (lane == 0) {
#pragma unroll
        for (int j = 0; j < KPT; j++)
#pragma unroll
            for (int s = 0; s < NSTAT; s++)
                sh[warp][j * NSTAT + s] = acc[j][s];
    }
    __syncthreads();

    if (tid < KPT * NSTAT) {
        float v = 0.0f;
#pragma unroll
        for (int w = 0; w < RTHREADS / 32; w++) v += sh[w][tid];
        // chunk-major write
        g_part[(size_t)chunk * ROWW + (b * KG + kg) * (KPT * NSTAT) + tid] = v;
    }
}

// ---------------------------------------------------------------------------
// Pass C: fused params-finalize + E-step (R7 structure, coalesced prologue).
// Prologue: 160 threads read g_part chunk-major (fully coalesced), 32 rounds.
// Main: 4 pixels/thread (two f32x2 pairs), 16 classes, q in registers.
// grid = (HW4/CTHREADS, BN), block = CTHREADS
// ---------------------------------------------------------------------------
__global__ __launch_bounds__(CTHREADS)
void gmm_estep_kernel(const float* __restrict__ I, float* __restrict__ out) {
    const int b = blockIdx.y;
    const int tid = threadIdx.x;
    const int p = blockIdx.x * CTHREADS + tid;

    __shared__ float raws[KN * NSTAT];
    __shared__ __align__(16) u64 spd[KN][NSTAT];

    // ---- fused pass B, stage 1: coalesced chunk-major reduction ----
    if (tid < KN * NSTAT) {
        const int row = b * (KN * NSTAT) + tid;
        float a = 0.0f;
#pragma unroll
        for (int c = 0; c < CHUNKS; c++)
            a += g_part[(size_t)c * ROWW + row];
        raws[tid] = a;
    }
    __syncthreads();

    // ---- fused pass B, stage 2: 3x3 inverse + log2-domain affine params ----
    if (tid < KN) {
        const float* s = &raws[tid * NSTAT];
        const float SP = s[0];
        const float rd = 1.0f / (1e-5f + SP);
        const float mu0 = s[1] * rd, mu1 = s[2] * rd, mu2 = s[3] * rd;

        const float c00 = (s[4] - 2.0f * mu0 * s[1] + SP * mu0 * mu0) * rd + 1e-3f;
        const float c01 = (s[5] - mu0 * s[2] - mu1 * s[1] + SP * mu0 * mu1) * rd;
        const float c02 = (s[6] - mu0 * s[3] - mu2 * s[1] + SP * mu0 * mu2) * rd;
        const float c11 = (s[7] - 2.0f * mu1 * s[2] + SP * mu1 * mu1) * rd + 1e-3f;
        const float c12 = (s[8] - mu1 * s[3] - mu2 * s[2] + SP * mu1 * mu2) * rd;
        const float c22 = (s[9] - 2.0f * mu2 * s[3] + SP * mu2 * mu2) * rd + 1e-3f;

        const float m00 = c11 * c22 - c12 * c12;
        const float m01 = c02 * c12 - c01 * c22;
        const float m02 = c01 * c12 - c02 * c11;
        const float det = c00 * m00 + c01 * m01 + c02 * m02;
        const float inv = 1.0f / det;

        const float i00 = m00 * inv;
        const float i01 = m01 * inv;
        const float i02 = m02 * inv;
        const float i11 = (c00 * c22 - c02 * c02) * inv;
        const float i12 = (c01 * c02 - c00 * c12) * inv;
        const float i22 = (c00 * c11 - c01 * c01) * inv;

        const float alpha = SP * (1.0f / (float)HW);
        const float logcoef = logf(alpha) - 0.5f * (3.0f * LOG_2PI + logf(det));

        const float g0 = i00 * mu0 + i01 * mu1 + i02 * mu2;
        const float g1 = i01 * mu0 + i11 * mu1 + i12 * mu2;
        const float g2 = i02 * mu0 + i12 * mu1 + i22 * mu2;
        const float Pmu = 0.5f * (i00 * mu0 * mu0 + i11 * mu1 * mu1 + i22 * mu2 * mu2)
                        + i01 * mu0 * mu1 + i02 * mu0 * mu2 + i12 * mu1 * mu2;

        u64* o = spd[tid];
        const float pc0 = (logcoef - Pmu) * LOG2E;
        const float pg0 = g0 * LOG2E, pg1 = g1 * LOG2E, pg2 = g2 * LOG2E;
        const float h00 = -0.5f * i00 * LOG2E, h11 = -0.5f * i11 * LOG2E, h22 = -0.5f * i22 * LOG2E;
        const float h01 = -i01 * LOG2E, h02 = -i02 * LOG2E, h12 = -i12 * LOG2E;
        o[0] = pack2(pc0, pc0);
        o[1] = pack2(pg0, pg0);
        o[2] = pack2(pg1, pg1);
        o[3] = pack2(pg2, pg2);
        o[4] = pack2(h00, h00);
        o[5] = pack2(h11, h11);
        o[6] = pack2(h22, h22);
        o[7] = pack2(h01, h01);
        o[8] = pack2(h02, h02);
        o[9] = pack2(h12, h12);
    }
    __syncthreads();

    // ---- E-step main: 4 pixels (2 f32x2 pairs), 16 classes, q in registers ----
    const float4 a0 = ((const float4*)(I + (size_t)(b * 3 + 0) * HW))[p];
    const float4 a1 = ((const float4*)(I + (size_t)(b * 3 + 1) * HW))[p];
    const float4 a2 = ((const float4*)(I + (size_t)(b * 3 + 2) * HW))[p];

    u64 X0[2], X1[2], X2[2], XX00[2], XX01[2], XX02[2], XX11[2], XX12[2], XX22[2];
#pragma unroll
    for (int pi = 0; pi < 2; pi++) {
        X0[pi] = pi ? pack2(a0.z, a0.w) : pack2(a0.x, a0.y);
        X1[pi] = pi ? pack2(a1.z, a1.w) : pack2(a1.x, a1.y);
        X2[pi] = pi ? pack2(a2.z, a2.w) : pack2(a2.x, a2.y);
        XX00[pi] = mul2(X0[pi], X0[pi]);
        XX01[pi] = mul2(X0[pi], X1[pi]);
        XX02[pi] = mul2(X0[pi], X2[pi]);
        XX11[pi] = mul2(X1[pi], X1[pi]);
        XX12[pi] = mul2(X1[pi], X2[pi]);
        XX22[pi] = mul2(X2[pi], X2[pi]);
    }

    u64 q0[KN], q1[KN];
    u64 sum0 = 0ull, sum1 = 0ull;
#pragma unroll
    for (int k = 0; k < KN; k++) {
        const ulonglong2* pr = (const ulonglong2*)spd[k];
        const ulonglong2 pA = pr[0];  // C0,  G0
        const ulonglong2 pB = pr[1];  // G1,  G2
        const ulonglong2 pC = pr[2];  // H00, H11
        const ulonglong2 pD = pr[3];  // H22, H01
        const ulonglong2 pE = pr[4];  // H02, H12

        {
            u64 ta = fma2(pA.y, X0[0], pA.x);
            ta = fma2(pB.x, X1[0], ta);
            ta = fma2(pB.y, X2[0], ta);
            ta = fma2(pC.x, XX00[0], ta);
            u64 tb = mul2(pC.y, XX11[0]);
            tb = fma2(pD.x, XX22[0], tb);
            tb = fma2(pD.y, XX01[0], tb);
            tb = fma2(pE.x, XX02[0], tb);
            tb = fma2(pE.y, XX12[0], tb);
            const u64 e = exp2_2(add2(ta, tb));
            q0[k] = e;
            sum0 = add2(sum0, e);
        }
        {
            u64 ta = fma2(pA.y, X0[1], pA.x);
            ta = fma2(pB.x, X1[1], ta);
            ta = fma2(pB.y, X2[1], ta);
            ta = fma2(pC.x, XX00[1], ta);
            u64 tb = mul2(pC.y, XX11[1]);
            tb = fma2(pD.x, XX22[1], tb);
            tb = fma2(pD.y, XX01[1], tb);
            tb = fma2(pE.x, XX02[1], tb);
            tb = fma2(pE.y, XX12[1], tb);
            const u64 e = exp2_2(add2(ta, tb));
            q1[k] = e;
            sum1 = add2(sum1, e);
        }
    }

    float s0, s1, s2, s3;
    unpack2(sum0, s0, s1);
    unpack2(sum1, s2, s3);
    const u64 R0 = pack2(rcp(1e-5f + s0), rcp(1e-5f + s1));
    const u64 R1 = pack2(rcp(1e-5f + s2), rcp(1e-5f + s3));

    float4* __restrict__ o4 = (float4*)(out + (size_t)b * KN * HW);
#pragma unroll
    for (int k = 0; k < KN; k++) {
        const u64 v01 = mul2(q0[k], R0);
        const u64 v23 = mul2(q1[k], R1);
        float4 v;
        unpack2(v01, v.x, v.y);
        unpack2(v23, v.z, v.w);
        __stcs(&o4[(size_t)k * HW4 + p], v);
    }
}

extern "C" void kernel_launch(void* const* d_in, const int* in_sizes, int n_in,
                              void* d_out, int out_size) {
    const float* Pij = (const float*)d_in[0];
    const float* I   = (const float*)d_in[1];
    float* out = (float*)d_out;

    dim3 gA(CHUNKS, KG, BN);
    gmm_reduce_kernel<<<gA, RTHREADS>>>(Pij, I);
    dim3 gC(HW4 / CTHREADS, BN);
    gmm_estep_kernel<<<gC, CTHREADS>>>(I, out);
}

// round 11
// speedup vs baseline: 1.7708x; 1.0042x over previous
#include <cuda_runtime.h>
#include <math.h>

// Problem constants
#define BN 4
#define KN 16
#define HW (512*512)
#define HW4 (HW/4)
#define HW2 (HW/2)
#define LOG_2PI 1.8378770664093453f
#define LOG2E 1.4426950408889634f

// Reduction config
#define KG 8            // k-groups
#define KPT 2           // k per thread (KG*KPT == KN)
#define CHUNKS 32       // pixel chunks per (b, kgroup)
#define RTHREADS 256
#define RITERS (HW4 / (CHUNKS * RTHREADS))   // = 8, exact
#define NSTAT 10
#define ROWW (BN * KG * KPT * NSTAT)         // 640: g_part row width (chunk-major)

#define CTHREADS 256    // pass C block

// Deterministic scratch (no allocations allowed).
// Chunk-major: g_part[chunk][ (b*KG+kg)*KPT*NSTAT + j*NSTAT + s ]
__device__ float g_part[CHUNKS * ROWW];

typedef unsigned long long u64;

__device__ __forceinline__ u64 pack2(float lo, float hi) {
    u64 r; asm("mov.b64 %0,{%1,%2};" : "=l"(r) : "f"(lo), "f"(hi)); return r;
}
__device__ __forceinline__ void unpack2(u64 v, float& lo, float& hi) {
    asm("mov.b64 {%0,%1},%2;" : "=f"(lo), "=f"(hi) : "l"(v));
}
__device__ __forceinline__ u64 fma2(u64 a, u64 b, u64 c) {
    u64 d; asm("fma.rn.f32x2 %0,%1,%2,%3;" : "=l"(d) : "l"(a), "l"(b), "l"(c)); return d;
}
__device__ __forceinline__ u64 mul2(u64 a, u64 b) {
    u64 d; asm("mul.rn.f32x2 %0,%1,%2;" : "=l"(d) : "l"(a), "l"(b)); return d;
}
__device__ __forceinline__ u64 add2(u64 a, u64 b) {
    u64 d; asm("add.rn.f32x2 %0,%1,%2;" : "=l"(d) : "l"(a), "l"(b)); return d;
}
__device__ __forceinline__ float ex2(float x) {
    float y; asm("ex2.approx.f32 %0,%1;" : "=f"(y) : "f"(x)); return y;
}
__device__ __forceinline__ u64 exp2_2(u64 t) {
    float lo, hi; unpack2(t, lo, hi);
    return pack2(ex2(lo), ex2(hi));
}
__device__ __forceinline__ float rcp(float x) {
    float y; asm("rcp.approx.f32 %0,%1;" : "=f"(y) : "f"(x)); return y;
}

// ---------------------------------------------------------------------------
// Pass A: per-(b,k) partial sufficient statistics, float4 loads, scalar FMA.
// grid = (CHUNKS, KG, BN), block = RTHREADS. No atomics -> deterministic.
// (Measured-best config, unchanged.)
// ---------------------------------------------------------------------------
__global__ __launch_bounds__(RTHREADS)
void gmm_reduce_kernel(const float* __restrict__ P, const float* __restrict__ I) {
    const int b = blockIdx.z, kg = blockIdx.y, chunk = blockIdx.x;
    const int tid = threadIdx.x;

    const float4* __restrict__ I0 = (const float4*)(I + (size_t)(b * 3 + 0) * HW);
    const float4* __restrict__ I1 = (const float4*)(I + (size_t)(b * 3 + 1) * HW);
    const float4* __restrict__ I2 = (const float4*)(I + (size_t)(b * 3 + 2) * HW);
    const float4* __restrict__ Pb = (const float4*)(P + ((size_t)b * KN + (size_t)kg * KPT) * HW);

    float acc[KPT][NSTAT];
#pragma unroll
    for (int j = 0; j < KPT; j++)
#pragma unroll
        for (int s = 0; s < NSTAT; s++) acc[j][s] = 0.0f;

    const int stride = CHUNKS * RTHREADS;
    int p = chunk * RTHREADS + tid;
#pragma unroll 2
    for (int it = 0; it < RITERS; it++, p += stride) {
        const float4 a0 = I0[p];
        const float4 a1 = I1[p];
        const float4 a2 = I2[p];
        float4 w[KPT];
#pragma unroll
        for (int j = 0; j < KPT; j++)
            w[j] = __ldcs(&Pb[(size_t)j * HW4 + p]);

        const float x0[4] = {a0.x, a0.y, a0.z, a0.w};
        const float x1[4] = {a1.x, a1.y, a1.z, a1.w};
        const float x2[4] = {a2.x, a2.y, a2.z, a2.w};
#pragma unroll
        for (int l = 0; l < 4; l++) {
            const float v0 = x0[l], v1 = x1[l], v2 = x2[l];
            const float p00 = v0 * v0, p01 = v0 * v1, p02 = v0 * v2;
            const float p11 = v1 * v1, p12 = v1 * v2, p22 = v2 * v2;
#pragma unroll
            for (int j = 0; j < KPT; j++) {
                const float wl = (l == 0) ? w[j].x : (l == 1) ? w[j].y : (l == 2) ? w[j].z : w[j].w;
                acc[j][0] += wl;
                acc[j][1] = fmaf(wl, v0, acc[j][1]);
                acc[j][2] = fmaf(wl, v1, acc[j][2]);
                acc[j][3] = fmaf(wl, v2, acc[j][3]);
                acc[j][4] = fmaf(wl, p00, acc[j][4]);
                acc[j][5] = fmaf(wl, p01, acc[j][5]);
                acc[j][6] = fmaf(wl, p02, acc[j][6]);
                acc[j][7] = fmaf(wl, p11, acc[j][7]);
                acc[j][8] = fmaf(wl, p12, acc[j][8]);
                acc[j][9] = fmaf(wl, p22, acc[j][9]);
            }
        }
    }

#pragma unroll
    for (int j = 0; j < KPT; j++)
#pragma unroll
        for (int s = 0; s < NSTAT; s++)
#pragma unroll
            for (int off = 16; off > 0; off >>= 1)
                acc[j][s] += __shfl_down_sync(0xffffffffu, acc[j][s], off);

    __shared__ float sh[RTHREADS / 32][KPT * NSTAT];
    const int warp = tid >> 5, lane = tid & 31;
    if (lane == 0) {
#pragma unroll
        for (int j = 0; j < KPT; j++)
#pragma unroll
            for (int s = 0; s < NSTAT; s++)
                sh[warp][j * NSTAT + s] = acc[j][s];
    }
    __syncthreads();

    if (tid < KPT * NSTAT) {
        float v = 0.0f;
#pragma unroll
        for (int w = 0; w < RTHREADS / 32; w++) v += sh[w][tid];
        // chunk-major write
        g_part[(size_t)chunk * ROWW + (b * KG + kg) * (KPT * NSTAT) + tid] = v;
    }
}

// ---------------------------------------------------------------------------
// Pass C: fused params-finalize + E-step.
// Prologue: coalesced chunk-major g_part reduction + 3x3 inverse.
// Main: 2 pixels/thread (one f32x2 pair), single sweep, q[16] in registers.
// grid = (HW2/CTHREADS, BN), block = CTHREADS
// ---------------------------------------------------------------------------
__global__ __launch_bounds__(CTHREADS)
void gmm_estep_kernel(const float* __restrict__ I, float* __restrict__ out) {
    const int b = blockIdx.y;
    const int tid = threadIdx.x;
    const int p = blockIdx.x * CTHREADS + tid;

    __shared__ float raws[KN * NSTAT];
    __shared__ __align__(16) u64 spd[KN][NSTAT];

    // ---- fused pass B, stage 1: coalesced chunk-major reduction ----
    if (tid < KN * NSTAT) {
        const int row = b * (KN * NSTAT) + tid;
        float a = 0.0f;
#pragma unroll
        for (int c = 0; c < CHUNKS; c++)
            a += g_part[(size_t)c * ROWW + row];
        raws[tid] = a;
    }
    __syncthreads();

    // ---- fused pass B, stage 2: 3x3 inverse + log2-domain affine params ----
    if (tid < KN) {
        const float* s = &raws[tid * NSTAT];
        const float SP = s[0];
        const float rd = 1.0f / (1e-5f + SP);
        const float mu0 = s[1] * rd, mu1 = s[2] * rd, mu2 = s[3] * rd;

        const float c00 = (s[4] - 2.0f * mu0 * s[1] + SP * mu0 * mu0) * rd + 1e-3f;
        const float c01 = (s[5] - mu0 * s[2] - mu1 * s[1] + SP * mu0 * mu1) * rd;
        const float c02 = (s[6] - mu0 * s[3] - mu2 * s[1] + SP * mu0 * mu2) * rd;
        const float c11 = (s[7] - 2.0f * mu1 * s[2] + SP * mu1 * mu1) * rd + 1e-3f;
        const float c12 = (s[8] - mu1 * s[3] - mu2 * s[2] + SP * mu1 * mu2) * rd;
        const float c22 = (s[9] - 2.0f * mu2 * s[3] + SP * mu2 * mu2) * rd + 1e-3f;

        const float m00 = c11 * c22 - c12 * c12;
        const float m01 = c02 * c12 - c01 * c22;
        const float m02 = c01 * c12 - c02 * c11;
        const float det = c00 * m00 + c01 * m01 + c02 * m02;
        const float inv = 1.0f / det;

        const float i00 = m00 * inv;
        const float i01 = m01 * inv;
        const float i02 = m02 * inv;
        const float i11 = (c00 * c22 - c02 * c02) * inv;
        const float i12 = (c01 * c02 - c00 * c12) * inv;
        const float i22 = (c00 * c11 - c01 * c01) * inv;

        const float alpha = SP * (1.0f / (float)HW);
        const float logcoef = logf(alpha) - 0.5f * (3.0f * LOG_2PI + logf(det));

        const float g0 = i00 * mu0 + i01 * mu1 + i02 * mu2;
        const float g1 = i01 * mu0 + i11 * mu1 + i12 * mu2;
        const float g2 = i02 * mu0 + i12 * mu1 + i22 * mu2;
        const float Pmu = 0.5f * (i00 * mu0 * mu0 + i11 * mu1 * mu1 + i22 * mu2 * mu2)
                        + i01 * mu0 * mu1 + i02 * mu0 * mu2 + i12 * mu1 * mu2;

        u64* o = spd[tid];
        const float pc0 = (logcoef - Pmu) * LOG2E;
        const float pg0 = g0 * LOG2E, pg1 = g1 * LOG2E, pg2 = g2 * LOG2E;
        const float h00 = -0.5f * i00 * LOG2E, h11 = -0.5f * i11 * LOG2E, h22 = -0.5f * i22 * LOG2E;
        const float h01 = -i01 * LOG2E, h02 = -i02 * LOG2E, h12 = -i12 * LOG2E;
        o[0] = pack2(pc0, pc0);
        o[1] = pack2(pg0, pg0);
        o[2] = pack2(pg1, pg1);
        o[3] = pack2(pg2, pg2);
        o[4] = pack2(h00, h00);
        o[5] = pack2(h11, h11);
        o[6] = pack2(h22, h22);
        o[7] = pack2(h01, h01);
        o[8] = pack2(h02, h02);
        o[9] = pack2(h12, h12);
    }
    __syncthreads();

    // ---- E-step main: 2 pixels (1 f32x2 pair), 16 classes, q in registers ----
    const float2 a0 = ((const float2*)(I + (size_t)(b * 3 + 0) * HW))[p];
    const float2 a1 = ((const float2*)(I + (size_t)(b * 3 + 1) * HW))[p];
    const float2 a2 = ((const float2*)(I + (size_t)(b * 3 + 2) * HW))[p];

    const u64 X0 = pack2(a0.x, a0.y);
    const u64 X1 = pack2(a1.x, a1.y);
    const u64 X2 = pack2(a2.x, a2.y);
    const u64 XX00 = mul2(X0, X0);
    const u64 XX01 = mul2(X0, X1);
    const u64 XX02 = mul2(X0, X2);
    const u64 XX11 = mul2(X1, X1);
    const u64 XX12 = mul2(X1, X2);
    const u64 XX22 = mul2(X2, X2);

    u64 q[KN];
    u64 sum = 0ull;
#pragma unroll
    for (int k = 0; k < KN; k++) {
        const ulonglong2* pr = (const ulonglong2*)spd[k];
        const ulonglong2 pA = pr[0];  // C0,  G0
        const ulonglong2 pB = pr[1];  // G1,  G2
        const ulonglong2 pC = pr[2];  // H00, H11
        const ulonglong2 pD = pr[3];  // H22, H01
        const ulonglong2 pE = pr[4];  // H02, H12

        u64 ta = fma2(pA.y, X0, pA.x);
        ta = fma2(pB.x, X1, ta);
        ta = fma2(pB.y, X2, ta);
        ta = fma2(pC.x, XX00, ta);
        u64 tb = mul2(pC.y, XX11);
        tb = fma2(pD.x, XX22, tb);
        tb = fma2(pD.y, XX01, tb);
        tb = fma2(pE.x, XX02, tb);
        tb = fma2(pE.y, XX12, tb);
        const u64 e = exp2_2(add2(ta, tb));
        q[k] = e;
        sum = add2(sum, e);
    }

    float s0, s1;
    unpack2(sum, s0, s1);
    const u64 R = pack2(rcp(1e-5f + s0), rcp(1e-5f + s1));

    float2* __restrict__ o2 = (float2*)(out + (size_t)b * KN * HW);
#pragma unroll
    for (int k = 0; k < KN; k++) {
        const u64 v = mul2(q[k], R);
        float2 f;
        unpack2(v, f.x, f.y);
        __stcs(&o2[(size_t)k * HW2 + p], f);
    }
}

extern "C" void kernel_launch(void* const* d_in, const int* in_sizes, int n_in,
                              void* d_out, int out_size) {
    const float* Pij = (const float*)d_in[0];
    const float* I   = (const float*)d_in[1];
    float* out = (float*)d_out;

    dim3 gA(CHUNKS, KG, BN);
    gmm_reduce_kernel<<<gA, RTHREADS>>>(Pij, I);
    dim3 gC(HW2 / CTHREADS, BN);
    gmm_estep_kernel<<<gC, CTHREADS>>>(I, out);
}